// round 3
// baseline (speedup 1.0000x reference)
#include <cuda_runtime.h>
#include <cuda_bf16.h>
#include <math.h>

#define BATCH 512
#define NGEN  4095
#define HID   256
#define KIN   768
#define NOBS  15
#define COUT  512
#define DIM   64
#define KMAX  240
#define HPITCH 65

// ---------------- scratch (device globals; no allocations allowed) ----------
__device__ float g_h[BATCH * HID];
__device__ float g_theta[BATCH * NGEN];
__device__ float g_q[BATCH * NOBS];

// wire pairs: combinations(range(6), 2) in order
__constant__ int c_wa[NOBS] = {0,0,0,0,0,1,1,1,1,2,2,2,3,3,4};
__constant__ int c_wb[NOBS] = {1,2,3,4,5,2,3,4,5,3,4,5,4,5,5};

__device__ __forceinline__ float silu_f(float x) { return x / (1.0f + expf(-x)); }

// ---------------------------------------------------------------------------
// Tiled fp32 GEMM: C = act(A@B + bias). A: MxK, B: KxN (row-major), C: MxN.
// M must be a multiple of BM; N, K arbitrary (guarded).
// ---------------------------------------------------------------------------
template<int BM, int BN, int BK, int TM, int TN, bool ACT>
__global__ void gemm_kernel(const float* __restrict__ A, const float* __restrict__ Bm,
                            const float* __restrict__ bias, float* __restrict__ C,
                            int M, int N, int K)
{
    constexpr int NT = (BM / TM) * (BN / TN);
    __shared__ float As[BK][BM + 1];
    __shared__ float Bs[BK][BN];

    const int tid = threadIdx.x;
    const int n0 = blockIdx.x * BN;
    const int m0 = blockIdx.y * BM;
    const int tx = tid % (BN / TN);
    const int ty = tid / (BN / TN);

    float acc[TM][TN];
#pragma unroll
    for (int i = 0; i < TM; i++)
#pragma unroll
        for (int j = 0; j < TN; j++) acc[i][j] = 0.0f;

    for (int kt = 0; kt < K; kt += BK) {
#pragma unroll 4
        for (int i = tid; i < BM * BK; i += NT) {
            int m = i / BK, kk = i % BK;
            As[kk][m] = (kt + kk < K) ? A[(m0 + m) * K + kt + kk] : 0.0f;
        }
#pragma unroll 4
        for (int i = tid; i < BK * BN; i += NT) {
            int kk = i / BN, n = i % BN;
            int gn = n0 + n;
            Bs[kk][n] = (gn < N && kt + kk < K) ? Bm[(kt + kk) * N + gn] : 0.0f;
        }
        __syncthreads();
#pragma unroll
        for (int kk = 0; kk < BK; ++kk) {
            float ra[TM], rb[TN];
#pragma unroll
            for (int i = 0; i < TM; i++) ra[i] = As[kk][ty * TM + i];
#pragma unroll
            for (int j = 0; j < TN; j++) rb[j] = Bs[kk][tx * TN + j];
#pragma unroll
            for (int i = 0; i < TM; i++)
#pragma unroll
                for (int j = 0; j < TN; j++) acc[i][j] += ra[i] * rb[j];
        }
        __syncthreads();
    }

#pragma unroll
    for (int i = 0; i < TM; i++) {
        int gm = m0 + ty * TM + i;
#pragma unroll
        for (int j = 0; j < TN; j++) {
            int gn = n0 + tx * TN + j;
            if (gn < N) {
                float v = acc[i][j] + bias[gn];
                if (ACT) v = silu_f(v);
                C[gm * N + gn] = v;
            }
        }
    }
}

// ---------------------------------------------------------------------------
// Physics kernel: theta -> H (WHT) -> psi = exp(iH)e0 (Chebyshev) -> q[15]
// One block per batch item, 128 threads. Dynamic smem.
// ---------------------------------------------------------------------------
__device__ __forceinline__ int spread6(int x) {
    return (x & 1) | ((x & 2) << 1) | ((x & 4) << 2) |
           ((x & 8) << 3) | ((x & 16) << 4) | ((x & 32) << 5);
}

__global__ void __launch_bounds__(128) physics_kernel(
    const float* __restrict__ theta_g,
    const float* __restrict__ Aoff, const float* __restrict__ Boff,
    const float* __restrict__ Ddiag, float* __restrict__ qout)
{
    extern __shared__ float sm[];
    // layout: float2-aligned things first
    float2* vbuf = (float2*)sm;                 // 3 * 64 float2
    float2* psiS = vbuf + 3 * DIM;              // 64 float2
    float*  th   = (float*)(psiS + DIM);        // 4096
    float*  Hre  = th + 4096;                   // 64*65
    float*  Him  = Hre + DIM * HPITCH;          // 64*65
    float*  cRe  = Him + DIM * HPITCH;          // KMAX+1
    float*  cIm  = cRe + (KMAX + 1);            // KMAX+1
    float*  red  = cIm + (KMAX + 1);            // 8

    __shared__ float sInvR, sR;
    __shared__ int sK;

    const int item = blockIdx.x;
    const int tid  = threadIdx.x;
    const int lane = tid & 31;
    const int warp = tid >> 5;

    // ---- Phase 1: load theta, compute sum of squares ----
    const float* tg = theta_g + (size_t)item * NGEN;
    float acc = 0.0f;
    if (tid == 0) th[0] = 0.0f;
    for (int i = tid; i < NGEN; i += 128) {
        float v = tg[i];
        th[i + 1] = v;
        acc += v * v;
    }
#pragma unroll
    for (int o = 16; o >= 1; o >>= 1) acc += __shfl_xor_sync(0xffffffffu, acc, o);
    if (lane == 0) red[warp] = acc;
    __syncthreads();
    if (tid == 0) {
        float S = red[0] + red[1] + red[2] + red[3];
        float R = 8.0f * sqrtf(S);
        if (R < 0.5f) R = 0.5f;
        int K = (int)ceilf(R + 8.0f * cbrtf(R) + 14.0f);
        if (K > KMAX) K = KMAX;
        if (K < 20) K = 20;
        sR = R; sInvR = 1.0f / R; sK = K;
    }
    __syncthreads();

    // ---- Phase 2: build H via per-X-mask WHT over Z-masks ----
    // H[c^a, c] = sum_b th[m(a,b)] * i^popc(a&b) * (-1)^popc(b&c)
#pragma unroll 1
    for (int t = 0; t < 16; ++t) {
        int a = (warp << 4) | t;
        float re[2], im[2];
#pragma unroll
        for (int h = 0; h < 2; ++h) {
            int b = lane + (h << 5);
            int m1 = (spread6(b) << 1) | spread6(a ^ b);
            float v = th[m1];
            int ph = __popc(a & b) & 3;
            re[h] = (ph == 0) ? v : ((ph == 2) ? -v : 0.0f);
            im[h] = (ph == 1) ? v : ((ph == 3) ? -v : 0.0f);
        }
#pragma unroll
        for (int st = 0; st < 5; ++st) {
            int msk = 1 << st;
            bool up = (lane & msk) != 0;
#pragma unroll
            for (int h = 0; h < 2; ++h) {
                float orr = __shfl_xor_sync(0xffffffffu, re[h], msk);
                float oii = __shfl_xor_sync(0xffffffffu, im[h], msk);
                re[h] = up ? (orr - re[h]) : (re[h] + orr);
                im[h] = up ? (oii - im[h]) : (im[h] + oii);
            }
        }
        float r0 = re[0] + re[1], r1 = re[0] - re[1];
        float i0 = im[0] + im[1], i1 = im[0] - im[1];
        int c0 = lane, c1 = lane | 32;
        Hre[(c0 ^ a) * HPITCH + c0] = r0; Him[(c0 ^ a) * HPITCH + c0] = i0;
        Hre[(c1 ^ a) * HPITCH + c1] = r1; Him[(c1 ^ a) * HPITCH + c1] = i1;
    }
    __syncthreads();

    // ---- Phase 3: Bessel coefficients via Miller backward recurrence ----
    if (tid == 0) {
        const int K = sK;
        const float twoInvR = 2.0f * sInvR;
        const int M = K + 16;
        float jp = 0.0f, jc = 1e-20f;
        for (int kk = M - 1; kk >= 0; --kk) {
            float jm = (float)(kk + 1) * twoInvR * jc - jp;
            jp = jc; jc = jm;
            if (fabsf(jc) > 1e30f) {
                jc *= 1e-30f; jp *= 1e-30f;
                for (int i = kk + 1; i <= K; ++i) cRe[i] *= 1e-30f;
            }
            if (kk <= K) cRe[kk] = jc;
        }
        float sum = cRe[0];
        for (int i = 2; i <= K; i += 2) sum += 2.0f * cRe[i];
        float scl = 1.0f / sum;
        for (int kk = 0; kk <= K; ++kk) {
            float J = cRe[kk] * scl;
            float tw = (kk == 0) ? J : 2.0f * J;
            int m = kk & 3;
            cRe[kk] = (m == 0) ? tw : ((m == 2) ? -tw : 0.0f);
            cIm[kk] = (m == 1) ? tw : ((m == 3) ? -tw : 0.0f);
        }
    }
    // ---- init Chebyshev vectors ----
    if (tid < DIM) {
        vbuf[tid]           = make_float2(0.0f, 0.0f);                       // vprev
        vbuf[DIM + tid]     = make_float2(tid == 0 ? 1.0f : 0.0f, 0.0f);     // vcur = e0
        psiS[tid]           = make_float2(0.0f, 0.0f);
    }
    __syncthreads();

    const int K = sK;
    const float invR = sInvR;
    float2* vprev = vbuf;
    float2* vcur  = vbuf + DIM;
    float2* vnext = vbuf + 2 * DIM;

    // ---- Phase 4: Chebyshev recurrence ----
    // warps 0,1: vnext = s*H*vcur - vprev ; warps 2,3: psi += c_{k-1} * vcur
    for (int k = 1; k <= K; ++k) {
        float s = ((k == 1) ? 1.0f : 2.0f) * invR;
        if (tid < DIM) {
            const int r = tid;
            const float* hr = Hre + r * HPITCH;
            const float* hi = Him + r * HPITCH;
            float ar0 = 0.0f, ai0 = 0.0f, ar1 = 0.0f, ai1 = 0.0f;
#pragma unroll 8
            for (int c = 0; c < DIM; c += 2) {
                float2 v0 = vcur[c];
                float2 v1 = vcur[c + 1];
                float h0r = hr[c],     h0i = hi[c];
                float h1r = hr[c + 1], h1i = hi[c + 1];
                ar0 += h0r * v0.x - h0i * v0.y;
                ai0 += h0r * v0.y + h0i * v0.x;
                ar1 += h1r * v1.x - h1i * v1.y;
                ai1 += h1r * v1.y + h1i * v1.x;
            }
            float2 vp = vprev[r];
            vnext[r] = make_float2(s * (ar0 + ar1) - vp.x, s * (ai0 + ai1) - vp.y);
        } else {
            const int r = tid - DIM;
            float2 v = vcur[r];
            float cr = cRe[k - 1], ci = cIm[k - 1];
            float2 p = psiS[r];
            psiS[r] = make_float2(p.x + cr * v.x - ci * v.y,
                                  p.y + cr * v.y + ci * v.x);
        }
        __syncthreads();
        float2* tp = vprev; vprev = vcur; vcur = vnext; vnext = tp;
    }
    // final term: psi += c_K * v_K  (v_K is now vcur)
    if (tid >= DIM) {
        const int r = tid - DIM;
        float2 v = vcur[r];
        float cr = cRe[K], ci = cIm[K];
        float2 p = psiS[r];
        psiS[r] = make_float2(p.x + cr * v.x - ci * v.y,
                              p.y + cr * v.y + ci * v.x);
    }
    __syncthreads();

    // ---- Phase 5: 15 two-local observables ----
    if (tid < NOBS) {
        const int w = tid;
        const int pA = 5 - c_wa[w], pB = 5 - c_wb[w];
        const int bitA = 1 << pA, bitB = 1 << pB;
        float d0 = 0, d1 = 0, d2 = 0, d3 = 0;
        float orr[6] = {0, 0, 0, 0, 0, 0};
        float oim[6] = {0, 0, 0, 0, 0, 0};
        for (int r = 0; r < 16; ++r) {
            int s = 0, rb = r;
#pragma unroll
            for (int p = 0; p < 6; ++p) {
                if (p != pA && p != pB) { s |= (rb & 1) << p; rb >>= 1; }
            }
            float2 p0 = psiS[s];
            float2 p1 = psiS[s | bitB];
            float2 p2 = psiS[s | bitA];
            float2 p3 = psiS[s | bitA | bitB];
            d0 += p0.x * p0.x + p0.y * p0.y;
            d1 += p1.x * p1.x + p1.y * p1.y;
            d2 += p2.x * p2.x + p2.y * p2.y;
            d3 += p3.x * p3.x + p3.y * p3.y;
            // pair order c: (1,0),(2,0),(2,1),(3,0),(3,1),(3,2) ; rho_ij = p_i * conj(p_j)
            orr[0] += p1.x * p0.x + p1.y * p0.y;  oim[0] += p1.y * p0.x - p1.x * p0.y;
            orr[1] += p2.x * p0.x + p2.y * p0.y;  oim[1] += p2.y * p0.x - p2.x * p0.y;
            orr[2] += p2.x * p1.x + p2.y * p1.y;  oim[2] += p2.y * p1.x - p2.x * p1.y;
            orr[3] += p3.x * p0.x + p3.y * p0.y;  oim[3] += p3.y * p0.x - p3.x * p0.y;
            orr[4] += p3.x * p1.x + p3.y * p1.y;  oim[4] += p3.y * p1.x - p3.x * p1.y;
            orr[5] += p3.x * p2.x + p3.y * p2.y;  oim[5] += p3.y * p2.x - p3.x * p2.y;
        }
        const float* Ao = Aoff + w * 6;
        const float* Bo = Boff + w * 6;
        const float* Dd = Ddiag + w * 4;
        float q = 2.0f * (Dd[1] * d0 + Dd[2] * d1 + Dd[3] * d2);
#pragma unroll
        for (int c = 0; c < 6; ++c)
            q += 2.0f * (Ao[c] * orr[c] + Bo[c] * oim[c]);
        qout[item * NOBS + w] = q;
    }
}

// ---------------------------------------------------------------------------
extern "C" void kernel_launch(void* const* d_in, const int* in_sizes, int n_in,
                              void* d_out, int out_size)
{
    const float* x     = (const float*)d_in[0];
    const float* W1    = (const float*)d_in[1];
    const float* b1    = (const float*)d_in[2];
    const float* W2    = (const float*)d_in[3];
    const float* b2    = (const float*)d_in[4];
    const float* Aoff  = (const float*)d_in[5];
    const float* Boff  = (const float*)d_in[6];
    const float* Ddiag = (const float*)d_in[7];
    const float* Wv1   = (const float*)d_in[8];
    const float* bv1   = (const float*)d_in[9];
    const float* Wv2   = (const float*)d_in[10];
    const float* bv2   = (const float*)d_in[11];
    float* out = (float*)d_out;

    float* hbuf;  cudaGetSymbolAddress((void**)&hbuf,  g_h);
    float* thbuf; cudaGetSymbolAddress((void**)&thbuf, g_theta);
    float* qbuf;  cudaGetSymbolAddress((void**)&qbuf,  g_q);

    // physics smem size
    const int smemPhys = (3 * DIM * 2 + DIM * 2 + 4096 + 2 * DIM * HPITCH +
                          2 * (KMAX + 1) + 8) * (int)sizeof(float);
    static int attrSet = 0;
    if (!attrSet) {
        cudaFuncSetAttribute(physics_kernel,
                             cudaFuncAttributeMaxDynamicSharedMemorySize, smemPhys);
        attrSet = 1;
    }

    // 1) enc hidden: silu(x @ W1 + b1) : 512x768 @ 768x256
    {
        dim3 grid(HID / 16, BATCH / 64);
        gemm_kernel<64, 16, 32, 4, 2, true><<<grid, 128>>>(x, W1, b1, hbuf, BATCH, HID, KIN);
    }
    // 2) theta = h @ W2 + b2 : 512x256 @ 256x4095
    {
        dim3 grid((NGEN + 63) / 64, BATCH / 64);
        gemm_kernel<64, 64, 16, 4, 4, false><<<grid, 256>>>(hbuf, W2, b2, thbuf, BATCH, NGEN, HID);
    }
    // 3) physics: theta -> q
    physics_kernel<<<BATCH, 128, smemPhys>>>(thbuf, Aoff, Boff, Ddiag, qbuf);
    // 4) head hidden: silu(q @ Wv1 + bv1) : 512x15 @ 15x256
    {
        dim3 grid(HID / 16, BATCH / 64);
        gemm_kernel<64, 16, 16, 4, 2, true><<<grid, 128>>>(qbuf, Wv1, bv1, hbuf, BATCH, HID, NOBS);
    }
    // 5) out = hh @ Wv2 + bv2 : 512x256 @ 256x512
    {
        dim3 grid(COUT / 32, BATCH / 64);
        gemm_kernel<64, 32, 32, 4, 4, false><<<grid, 128>>>(hbuf, Wv2, bv2, out, BATCH, COUT, HID);
    }
}

// round 8
// speedup vs baseline: 1.4466x; 1.4466x over previous
#include <cuda_runtime.h>
#include <cuda_bf16.h>
#include <math.h>

#define BATCH 512
#define NGEN  4095
#define HID   256
#define KIN   768
#define NOBS  15
#define COUT  512
#define DIM   64
#define KMAX  128
#define HPITCH 65

// ---------------- scratch (device globals; no allocations allowed) ----------
__device__ float g_h[BATCH * HID];
__device__ float g_theta[BATCH * NGEN];
__device__ float g_q[BATCH * NOBS];

// wire pairs: combinations(range(6), 2) in order
__constant__ int c_wa[NOBS] = {0,0,0,0,0,1,1,1,1,2,2,2,3,3,4};
__constant__ int c_wb[NOBS] = {1,2,3,4,5,2,3,4,5,3,4,5,4,5,5};

__device__ __forceinline__ float silu_f(float x) { return x / (1.0f + expf(-x)); }

// packed f32x2 helpers (SASS: FFMA2 — only reachable via PTX fma.rn.f32x2)
__device__ __forceinline__ unsigned long long pk2(float a, float b) {
    unsigned long long r;
    asm("mov.b64 %0,{%1,%2};" : "=l"(r) : "f"(a), "f"(b));
    return r;
}
__device__ __forceinline__ void upk2(unsigned long long v, float& a, float& b) {
    asm("mov.b64 {%0,%1},%2;" : "=f"(a), "=f"(b) : "l"(v));
}
#define FMA2(acc, a, b) asm("fma.rn.f32x2 %0, %1, %2, %0;" : "+l"(acc) : "l"(a), "l"(b))

// ---------------------------------------------------------------------------
// Tiled fp32 GEMM: C = act(A@B + bias). A: MxK, B: KxN (row-major), C: MxN.
// ---------------------------------------------------------------------------
template<int BM, int BN, int BK, int TM, int TN, bool ACT>
__global__ void gemm_kernel(const float* __restrict__ A, const float* __restrict__ Bm,
                            const float* __restrict__ bias, float* __restrict__ C,
                            int M, int N, int K)
{
    constexpr int NT = (BM / TM) * (BN / TN);
    __shared__ float As[BK][BM + 1];
    __shared__ float Bs[BK][BN];

    const int tid = threadIdx.x;
    const int n0 = blockIdx.x * BN;
    const int m0 = blockIdx.y * BM;
    const int tx = tid % (BN / TN);
    const int ty = tid / (BN / TN);

    float acc[TM][TN];
#pragma unroll
    for (int i = 0; i < TM; i++)
#pragma unroll
        for (int j = 0; j < TN; j++) acc[i][j] = 0.0f;

    for (int kt = 0; kt < K; kt += BK) {
#pragma unroll 4
        for (int i = tid; i < BM * BK; i += NT) {
            int m = i / BK, kk = i % BK;
            As[kk][m] = (kt + kk < K) ? A[(m0 + m) * K + kt + kk] : 0.0f;
        }
#pragma unroll 4
        for (int i = tid; i < BK * BN; i += NT) {
            int kk = i / BN, n = i % BN;
            int gn = n0 + n;
            Bs[kk][n] = (gn < N && kt + kk < K) ? Bm[(kt + kk) * N + gn] : 0.0f;
        }
        __syncthreads();
#pragma unroll
        for (int kk = 0; kk < BK; ++kk) {
            float ra[TM], rb[TN];
#pragma unroll
            for (int i = 0; i < TM; i++) ra[i] = As[kk][ty * TM + i];
#pragma unroll
            for (int j = 0; j < TN; j++) rb[j] = Bs[kk][tx * TN + j];
#pragma unroll
            for (int i = 0; i < TM; i++)
#pragma unroll
                for (int j = 0; j < TN; j++) acc[i][j] += ra[i] * rb[j];
        }
        __syncthreads();
    }

#pragma unroll
    for (int i = 0; i < TM; i++) {
        int gm = m0 + ty * TM + i;
#pragma unroll
        for (int j = 0; j < TN; j++) {
            int gn = n0 + tx * TN + j;
            if (gn < N) {
                float v = acc[i][j] + bias[gn];
                if (ACT) v = silu_f(v);
                C[gm * N + gn] = v;
            }
        }
    }
}

// ---------------------------------------------------------------------------
// Physics kernel v2: theta -> H (WHT, into registers) -> psi = exp(iH)e0
// (Chebyshev, spectral-norm-adaptive K + unitarity certificate) -> q[15]
// One block per batch item, 128 threads.
// ---------------------------------------------------------------------------
__device__ __forceinline__ int spread6(int x) {
    return (x & 1) | ((x & 2) << 1) | ((x & 4) << 2) |
           ((x & 8) << 3) | ((x & 16) << 4) | ((x & 32) << 5);
}

__global__ void __launch_bounds__(128, 4) physics_kernel(
    const float* __restrict__ theta_g,
    const float* __restrict__ Aoff, const float* __restrict__ Boff,
    const float* __restrict__ Ddiag, float* __restrict__ qout)
{
    extern __shared__ float sm[];
    float* th   = sm;                         // 4096
    float* Hre  = th + 4096;                  // 64*65
    float* Him  = Hre + DIM * HPITCH;         // 64*65
    float* vre  = Him + DIM * HPITCH;         // 3*64 (SoA ring)
    float* vim  = vre + 3 * DIM;              // 3*64
    float* psr  = vim + 3 * DIM;              // 64
    float* psii = psr + DIM;                  // 64
    float* cRe  = psii + DIM;                 // KMAX+1
    float* cIm  = cRe + (KMAX + 1);           // KMAX+1
    float* red  = cIm + (KMAX + 1);           // 16

    __shared__ float sInvR, sRbase;
    __shared__ int sK, sOK;

    const int item = blockIdx.x;
    const int tid  = threadIdx.x;
    const int lane = tid & 31;
    const int warp = tid >> 5;

    // ---- Phase 1: load theta, compute ||theta||^2 ----
    const float* tg = theta_g + (size_t)item * NGEN;
    float acc = 0.0f;
    if (tid == 0) th[0] = 0.0f;
    for (int i = tid; i < NGEN; i += 128) {
        float v = tg[i];
        th[i + 1] = v;
        acc += v * v;
    }
#pragma unroll
    for (int o = 16; o >= 1; o >>= 1) acc += __shfl_xor_sync(0xffffffffu, acc, o);
    if (lane == 0) red[warp] = acc;
    __syncthreads();
    if (tid == 0) {
        float S = red[0] + red[1] + red[2] + red[3];
        // GUE: ||H||_2 ~= 2*||theta||_2 ; margin for Tracy-Widom fluctuation
        sRbase = 2.3f * sqrtf(S) + 1.5f;
    }

    // ---- Phase 2: build H via per-X-mask WHT over Z-masks ----
#pragma unroll 1
    for (int t = 0; t < 16; ++t) {
        int a = (warp << 4) | t;
        float re[2], im[2];
#pragma unroll
        for (int h = 0; h < 2; ++h) {
            int b = lane + (h << 5);
            int m1 = (spread6(b) << 1) | spread6(a ^ b);
            float v = th[m1];
            int ph = __popc(a & b) & 3;
            re[h] = (ph == 0) ? v : ((ph == 2) ? -v : 0.0f);
            im[h] = (ph == 1) ? v : ((ph == 3) ? -v : 0.0f);
        }
#pragma unroll
        for (int st = 0; st < 5; ++st) {
            int msk = 1 << st;
            bool up = (lane & msk) != 0;
#pragma unroll
            for (int h = 0; h < 2; ++h) {
                float orr = __shfl_xor_sync(0xffffffffu, re[h], msk);
                float oii = __shfl_xor_sync(0xffffffffu, im[h], msk);
                re[h] = up ? (orr - re[h]) : (re[h] + orr);
                im[h] = up ? (oii - im[h]) : (im[h] + oii);
            }
        }
        float r0v = re[0] + re[1], r1v = re[0] - re[1];
        float i0v = im[0] + im[1], i1v = im[0] - im[1];
        int c0 = lane, c1 = lane | 32;
        Hre[(c0 ^ a) * HPITCH + c0] = r0v; Him[(c0 ^ a) * HPITCH + c0] = i0v;
        Hre[(c1 ^ a) * HPITCH + c1] = r1v; Him[(c1 ^ a) * HPITCH + c1] = i1v;
    }
    __syncthreads();

    // ---- Phase 2b: load this thread's H slice into packed registers ----
    // thread layout: qc = col quarter (16 cols), rp -> rows 2rp, 2rp+1
    const int qc = tid & 3, rp = tid >> 2;
    const int r0 = rp * 2, r1 = r0 + 1, cb = qc * 16;
    unsigned long long Ar0[8], Ai0[8], Ar1[8], Ai1[8];
#pragma unroll
    for (int p = 0; p < 8; ++p) {
        int c = cb + 2 * p;
        Ar0[p] = pk2(Hre[r0 * HPITCH + c], Hre[r0 * HPITCH + c + 1]);
        Ai0[p] = pk2(Him[r0 * HPITCH + c], Him[r0 * HPITCH + c + 1]);
        Ar1[p] = pk2(Hre[r1 * HPITCH + c], Hre[r1 * HPITCH + c + 1]);
        Ai1[p] = pk2(Him[r1 * HPITCH + c], Him[r1 * HPITCH + c + 1]);
    }

    // ---- Attempt loop: Chebyshev with adaptive R; retry on certificate fail ----
    for (int att = 0; att < 3; ++att) {
        if (tid == 0) {
            float R = sRbase;
            for (int i = 0; i < att; ++i) R *= 1.45f;
            // K from J_K(R) < ~1e-10 : K*ln(2K/(e*R)) > 23
            int k = (int)ceilf(R) + 2; if (k < 10) k = 10;
            while (k < KMAX - 8 && (float)k * logf(0.73576f * (float)k / R) < 23.0f) k += 2;
            k += 6; if (k > KMAX) k = KMAX;
            sK = k; sInvR = 1.0f / R;
            // Bessel J_0..J_k(R) via Miller backward recurrence
            const float twoInvR = 2.0f / R;
            const int M = k + 14;
            float jp = 0.0f, jc = 1e-20f;
            for (int kk = M - 1; kk >= 0; --kk) {
                float jm = (float)(kk + 1) * twoInvR * jc - jp;
                jp = jc; jc = jm;
                if (fabsf(jc) > 1e30f) {
                    jc *= 1e-30f; jp *= 1e-30f;
                    for (int i = kk + 1; i <= k; ++i) cRe[i] *= 1e-30f;
                }
                if (kk <= k) cRe[kk] = jc;
            }
            float sum = cRe[0];
            for (int i = 2; i <= k; i += 2) sum += 2.0f * cRe[i];
            float scl = 1.0f / sum;
            for (int kk = 0; kk <= k; ++kk) {
                float tw = ((kk == 0) ? 1.0f : 2.0f) * cRe[kk] * scl;
                int m4 = kk & 3;   // i^k twist
                cRe[kk] = (m4 == 0) ? tw : ((m4 == 2) ? -tw : 0.0f);
                cIm[kk] = (m4 == 1) ? tw : ((m4 == 3) ? -tw : 0.0f);
            }
        }
        if (tid < DIM) {
            vre[tid] = 0.0f;        vim[tid] = 0.0f;              // v_{-1} = 0
            vre[DIM + tid] = (tid == 0) ? 1.0f : 0.0f;            // v_0 = e0
            vim[DIM + tid] = 0.0f;
            psr[tid] = 0.0f;        psii[tid] = 0.0f;
        }
        __syncthreads();

        const int K = sK;
        const float invR = sInvR;
        int ip = 0, ic = 1, in_ = 2;

        for (int k = 1; k <= K; ++k) {
            const float* xr = vre + ic * DIM;
            const float* xi = vim + ic * DIM;
            unsigned long long aR0 = 0, aM0 = 0, aIa0 = 0, aIb0 = 0;
            unsigned long long aR1 = 0, aM1 = 0, aIa1 = 0, aIb1 = 0;
#pragma unroll
            for (int p = 0; p < 8; ++p) {
                unsigned long long Vr = *(const unsigned long long*)(xr + cb + 2 * p);
                unsigned long long Vi = *(const unsigned long long*)(xi + cb + 2 * p);
                FMA2(aR0,  Ar0[p], Vr); FMA2(aM0,  Ai0[p], Vi);
                FMA2(aIa0, Ar0[p], Vi); FMA2(aIb0, Ai0[p], Vr);
                FMA2(aR1,  Ar1[p], Vr); FMA2(aM1,  Ai1[p], Vi);
                FMA2(aIa1, Ar1[p], Vi); FMA2(aIb1, Ai1[p], Vr);
            }
            float u, v, hr0, hi0, hr1, hi1;
            upk2(aR0, u, v);  hr0 = u + v;  upk2(aM0, u, v);  hr0 -= u + v;
            upk2(aIa0, u, v); hi0 = u + v;  upk2(aIb0, u, v); hi0 += u + v;
            upk2(aR1, u, v);  hr1 = u + v;  upk2(aM1, u, v);  hr1 -= u + v;
            upk2(aIa1, u, v); hi1 = u + v;  upk2(aIb1, u, v); hi1 += u + v;
#pragma unroll
            for (int m = 1; m <= 2; m <<= 1) {
                hr0 += __shfl_xor_sync(0xffffffffu, hr0, m);
                hi0 += __shfl_xor_sync(0xffffffffu, hi0, m);
                hr1 += __shfl_xor_sync(0xffffffffu, hr1, m);
                hi1 += __shfl_xor_sync(0xffffffffu, hi1, m);
            }
            if (qc == 0) {
                float s = ((k == 1) ? 1.0f : 2.0f) * invR;
                vre[in_ * DIM + r0] = s * hr0 - vre[ip * DIM + r0];
                vim[in_ * DIM + r0] = s * hi0 - vim[ip * DIM + r0];
                vre[in_ * DIM + r1] = s * hr1 - vre[ip * DIM + r1];
                vim[in_ * DIM + r1] = s * hi1 - vim[ip * DIM + r1];
            } else if (qc == 1) {
                float cr = cRe[k - 1], ci = cIm[k - 1];
                float a = xr[r0], b = xi[r0];
                psr[r0] += cr * a - ci * b;  psii[r0] += cr * b + ci * a;
                a = xr[r1]; b = xi[r1];
                psr[r1] += cr * a - ci * b;  psii[r1] += cr * b + ci * a;
            }
            __syncthreads();
            int t = ip; ip = ic; ic = in_; in_ = t;
        }
        // final term: psi += c_K * v_K  (v_K now at ic)
        if (qc == 1) {
            float cr = cRe[K], ci = cIm[K];
            const float* xr = vre + ic * DIM;
            const float* xi = vim + ic * DIM;
            float a = xr[r0], b = xi[r0];
            psr[r0] += cr * a - ci * b;  psii[r0] += cr * b + ci * a;
            a = xr[r1]; b = xi[r1];
            psr[r1] += cr * a - ci * b;  psii[r1] += cr * b + ci * a;
        }
        __syncthreads();

        // ---- unitarity certificate: ||psi||^2 must be 1 ----
        if (tid < 32) {
            float a = psr[tid], b = psii[tid], c = psr[tid + 32], d = psii[tid + 32];
            float n = a * a + b * b + c * c + d * d;
#pragma unroll
            for (int o = 16; o >= 1; o >>= 1) n += __shfl_xor_sync(0xffffffffu, n, o);
            if (tid == 0) sOK = (fabsf(n - 1.0f) < 2e-4f) ? 1 : 0;
        }
        __syncthreads();
        if (sOK) break;
    }

    // ---- Phase 5: 15 two-local observables ----
    if (tid < NOBS) {
        const int w = tid;
        const int pA = 5 - c_wa[w], pB = 5 - c_wb[w];
        const int bitA = 1 << pA, bitB = 1 << pB;
        float d0 = 0, d1 = 0, d2 = 0, d3 = 0;
        float orr[6] = {0, 0, 0, 0, 0, 0};
        float oim[6] = {0, 0, 0, 0, 0, 0};
        for (int r = 0; r < 16; ++r) {
            int s = 0, rb = r;
#pragma unroll
            for (int p = 0; p < 6; ++p) {
                if (p != pA && p != pB) { s |= (rb & 1) << p; rb >>= 1; }
            }
            float2 p0 = make_float2(psr[s],               psii[s]);
            float2 p1 = make_float2(psr[s | bitB],        psii[s | bitB]);
            float2 p2 = make_float2(psr[s | bitA],        psii[s | bitA]);
            float2 p3 = make_float2(psr[s | bitA | bitB], psii[s | bitA | bitB]);
            d0 += p0.x * p0.x + p0.y * p0.y;
            d1 += p1.x * p1.x + p1.y * p1.y;
            d2 += p2.x * p2.x + p2.y * p2.y;
            d3 += p3.x * p3.x + p3.y * p3.y;
            orr[0] += p1.x * p0.x + p1.y * p0.y;  oim[0] += p1.y * p0.x - p1.x * p0.y;
            orr[1] += p2.x * p0.x + p2.y * p0.y;  oim[1] += p2.y * p0.x - p2.x * p0.y;
            orr[2] += p2.x * p1.x + p2.y * p1.y;  oim[2] += p2.y * p1.x - p2.x * p1.y;
            orr[3] += p3.x * p0.x + p3.y * p0.y;  oim[3] += p3.y * p0.x - p3.x * p0.y;
            orr[4] += p3.x * p1.x + p3.y * p1.y;  oim[4] += p3.y * p1.x - p3.x * p1.y;
            orr[5] += p3.x * p2.x + p3.y * p2.y;  oim[5] += p3.y * p2.x - p3.x * p2.y;
        }
        const float* Ao = Aoff + w * 6;
        const float* Bo = Boff + w * 6;
        const float* Dd = Ddiag + w * 4;
        float q = 2.0f * (Dd[1] * d0 + Dd[2] * d1 + Dd[3] * d2);
#pragma unroll
        for (int c = 0; c < 6; ++c)
            q += 2.0f * (Ao[c] * orr[c] + Bo[c] * oim[c]);
        qout[item * NOBS + w] = q;
    }
}

// ---------------------------------------------------------------------------
extern "C" void kernel_launch(void* const* d_in, const int* in_sizes, int n_in,
                              void* d_out, int out_size)
{
    const float* x     = (const float*)d_in[0];
    const float* W1    = (const float*)d_in[1];
    const float* b1    = (const float*)d_in[2];
    const float* W2    = (const float*)d_in[3];
    const float* b2    = (const float*)d_in[4];
    const float* Aoff  = (const float*)d_in[5];
    const float* Boff  = (const float*)d_in[6];
    const float* Ddiag = (const float*)d_in[7];
    const float* Wv1   = (const float*)d_in[8];
    const float* bv1   = (const float*)d_in[9];
    const float* Wv2   = (const float*)d_in[10];
    const float* bv2   = (const float*)d_in[11];
    float* out = (float*)d_out;

    float* hbuf;  cudaGetSymbolAddress((void**)&hbuf,  g_h);
    float* thbuf; cudaGetSymbolAddress((void**)&thbuf, g_theta);
    float* qbuf;  cudaGetSymbolAddress((void**)&qbuf,  g_q);

    const int smemPhys = (4096 + 2 * DIM * HPITCH + 6 * DIM + 2 * DIM +
                          2 * (KMAX + 1) + 16) * (int)sizeof(float);
    static int attrSet = 0;
    if (!attrSet) {
        cudaFuncSetAttribute(physics_kernel,
                             cudaFuncAttributeMaxDynamicSharedMemorySize, smemPhys);
        attrSet = 1;
    }

    // 1) enc hidden: silu(x @ W1 + b1) : 512x768 @ 768x256
    {
        dim3 grid(HID / 16, BATCH / 64);
        gemm_kernel<64, 16, 32, 4, 2, true><<<grid, 128>>>(x, W1, b1, hbuf, BATCH, HID, KIN);
    }
    // 2) theta = h @ W2 + b2 : 512x256 @ 256x4095
    {
        dim3 grid((NGEN + 63) / 64, BATCH / 64);
        gemm_kernel<64, 64, 16, 4, 4, false><<<grid, 256>>>(hbuf, W2, b2, thbuf, BATCH, NGEN, HID);
    }
    // 3) physics: theta -> q
    physics_kernel<<<BATCH, 128, smemPhys>>>(thbuf, Aoff, Boff, Ddiag, qbuf);
    // 4) head hidden: silu(q @ Wv1 + bv1) : 512x15 @ 15x256
    {
        dim3 grid(HID / 16, BATCH / 64);
        gemm_kernel<64, 16, 16, 4, 2, true><<<grid, 128>>>(qbuf, Wv1, bv1, hbuf, BATCH, HID, NOBS);
    }
    // 5) out = hh @ Wv2 + bv2 : 512x256 @ 256x512
    {
        dim3 grid(COUT / 32, BATCH / 64);
        gemm_kernel<64, 32, 32, 4, 4, false><<<grid, 128>>>(hbuf, Wv2, bv2, out, BATCH, COUT, HID);
    }
}

// round 10
// speedup vs baseline: 1.5749x; 1.0887x over previous
#include <cuda_runtime.h>
#include <cuda_bf16.h>
#include <cstdint>
#include <math.h>

#define BATCH 512
#define NGEN  4095
#define HID   256
#define KIN   768
#define NOBS  15
#define COUT  512
#define DIM   64
#define KMAX  128
#define HPITCH 65
#define K3    768          // 3-product split K
#define NPAD  4096

// ---------------- scratch (device globals; no allocations allowed) ----------
__device__ float g_h[BATCH * HID];
__device__ float g_theta[BATCH * NGEN];
__device__ float g_q[BATCH * NOBS];
__device__ __nv_bfloat16 g_A2[BATCH * K3];        // [Ah | Ah | Al]
__device__ __nv_bfloat16 g_B2T[NPAD * K3];        // row n: [Bh(k) | Bl(k) | Bh(k)]

// wire pairs: combinations(range(6), 2) in order
__constant__ int c_wa[NOBS] = {0,0,0,0,0,1,1,1,1,2,2,2,3,3,4};
__constant__ int c_wb[NOBS] = {1,2,3,4,5,2,3,4,5,3,4,5,4,5,5};

__device__ __forceinline__ float silu_f(float x) { return x / (1.0f + expf(-x)); }

// packed f32x2 helpers (SASS: FFMA2 — only reachable via PTX fma.rn.f32x2)
__device__ __forceinline__ unsigned long long pk2(float a, float b) {
    unsigned long long r;
    asm("mov.b64 %0,{%1,%2};" : "=l"(r) : "f"(a), "f"(b));
    return r;
}
__device__ __forceinline__ void upk2(unsigned long long v, float& a, float& b) {
    asm("mov.b64 {%0,%1},%2;" : "=f"(a), "=f"(b) : "l"(v));
}
#define FMA2(acc, a, b) asm("fma.rn.f32x2 %0, %1, %2, %0;" : "+l"(acc) : "l"(a), "l"(b))

// ---------------------------------------------------------------------------
// Tiled fp32 GEMM (used for GEMM1 and GEMM5)
// ---------------------------------------------------------------------------
template<int BM, int BN, int BK, int TM, int TN, bool ACT>
__global__ void gemm_kernel(const float* __restrict__ A, const float* __restrict__ Bm,
                            const float* __restrict__ bias, float* __restrict__ C,
                            int M, int N, int K)
{
    constexpr int NT = (BM / TM) * (BN / TN);
    __shared__ float As[BK][BM + 1];
    __shared__ float Bs[BK][BN];

    const int tid = threadIdx.x;
    const int n0 = blockIdx.x * BN;
    const int m0 = blockIdx.y * BM;
    const int tx = tid % (BN / TN);
    const int ty = tid / (BN / TN);

    float acc[TM][TN];
#pragma unroll
    for (int i = 0; i < TM; i++)
#pragma unroll
        for (int j = 0; j < TN; j++) acc[i][j] = 0.0f;

    for (int kt = 0; kt < K; kt += BK) {
#pragma unroll 4
        for (int i = tid; i < BM * BK; i += NT) {
            int m = i / BK, kk = i % BK;
            As[kk][m] = (kt + kk < K) ? A[(m0 + m) * K + kt + kk] : 0.0f;
        }
#pragma unroll 4
        for (int i = tid; i < BK * BN; i += NT) {
            int kk = i / BN, n = i % BN;
            int gn = n0 + n;
            Bs[kk][n] = (gn < N && kt + kk < K) ? Bm[(kt + kk) * N + gn] : 0.0f;
        }
        __syncthreads();
#pragma unroll
        for (int kk = 0; kk < BK; ++kk) {
            float ra[TM], rb[TN];
#pragma unroll
            for (int i = 0; i < TM; i++) ra[i] = As[kk][ty * TM + i];
#pragma unroll
            for (int j = 0; j < TN; j++) rb[j] = Bs[kk][tx * TN + j];
#pragma unroll
            for (int i = 0; i < TM; i++)
#pragma unroll
                for (int j = 0; j < TN; j++) acc[i][j] += ra[i] * rb[j];
        }
        __syncthreads();
    }

#pragma unroll
    for (int i = 0; i < TM; i++) {
        int gm = m0 + ty * TM + i;
#pragma unroll
        for (int j = 0; j < TN; j++) {
            int gn = n0 + tx * TN + j;
            if (gn < N) {
                float v = acc[i][j] + bias[gn];
                if (ACT) v = silu_f(v);
                C[gm * N + gn] = v;
            }
        }
    }
}

// ---------------------------------------------------------------------------
// Split A (hidden activations) into [Ah | Ah | Al] bf16
// ---------------------------------------------------------------------------
__global__ void splitA_kernel(const float* __restrict__ h, __nv_bfloat16* __restrict__ A2)
{
    int idx = blockIdx.x * 256 + threadIdx.x;   // 512*256 total
    int m = idx >> 8, k = idx & 255;
    float v = h[idx];
    __nv_bfloat16 hi = __float2bfloat16_rn(v);
    __nv_bfloat16 lo = __float2bfloat16_rn(v - __bfloat162float(hi));
    __nv_bfloat16* row = A2 + (size_t)m * K3;
    row[k] = hi; row[256 + k] = hi; row[512 + k] = lo;
}

// ---------------------------------------------------------------------------
// Transpose+split W2 (256 x 4095 fp32) into B2T (4096 x 768 bf16, n-major)
// row n: [Bh(k=0..255) | Bl | Bh]
// ---------------------------------------------------------------------------
__global__ void transposeB_kernel(const float* __restrict__ W2, __nv_bfloat16* __restrict__ B2T)
{
    __shared__ float tile[32][33];
    const int n0 = blockIdx.x * 32;   // 128 blocks
    const int k0 = blockIdx.y * 32;   // 8 blocks
    const int tx = threadIdx.x, ty = threadIdx.y;   // (32, 8)
#pragma unroll
    for (int j = 0; j < 4; ++j) {
        int k = k0 + ty + j * 8;
        int n = n0 + tx;
        tile[ty + j * 8][tx] = (n < NGEN) ? W2[(size_t)k * NGEN + n] : 0.0f;
    }
    __syncthreads();
#pragma unroll
    for (int j = 0; j < 4; ++j) {
        int n = n0 + ty + j * 8;
        int k = k0 + tx;
        float v = tile[tx][ty + j * 8];
        __nv_bfloat16 hi = __float2bfloat16_rn(v);
        __nv_bfloat16 lo = __float2bfloat16_rn(v - __bfloat162float(hi));
        __nv_bfloat16* row = B2T + (size_t)n * K3;
        row[k] = hi; row[256 + k] = lo; row[512 + k] = hi;
    }
}

// ---------------------------------------------------------------------------
// Tensor-core GEMM2: theta(512x4095) = A2(512x768) @ B2T^T + b2
// BM=64, BN=128, BK=32, 256 threads (8 warps, 2x4), warp tile 32x32.
// ---------------------------------------------------------------------------
__device__ __forceinline__ unsigned int smem_u32(const void* p) {
    return (unsigned int)__cvta_generic_to_shared(p);
}

__global__ void __launch_bounds__(256) mma_gemm2(
    const __nv_bfloat16* __restrict__ A2, const __nv_bfloat16* __restrict__ B2T,
    const float* __restrict__ bias, float* __restrict__ C)
{
    __shared__ __align__(16) __nv_bfloat16 As[64 * 40];
    __shared__ __align__(16) __nv_bfloat16 Bs[128 * 40];

    const int tid  = threadIdx.x;
    const int lane = tid & 31;
    const int w    = tid >> 5;
    const int wm   = w >> 2;          // 0..1 (rows)
    const int wn   = w & 3;           // 0..3 (cols)
    const int m0   = blockIdx.y * 64;
    const int n0   = blockIdx.x * 128;

    float acc[2][4][4];
#pragma unroll
    for (int i = 0; i < 2; i++)
#pragma unroll
        for (int j = 0; j < 4; j++)
#pragma unroll
            for (int r = 0; r < 4; r++) acc[i][j][r] = 0.0f;

    for (int kt = 0; kt < K3; kt += 32) {
        // As: 64 rows x 32 k = 256 16B-chunks; 1 per thread
        {
            int row = tid >> 2, kc = (tid & 3) * 8;
            *(uint4*)(As + row * 40 + kc) =
                *(const uint4*)(A2 + (size_t)(m0 + row) * K3 + kt + kc);
        }
        // Bs: 128 rows x 32 k = 512 chunks; 2 per thread
#pragma unroll
        for (int cc = 0; cc < 2; ++cc) {
            int c = tid + cc * 256;
            int row = c >> 2, kc = (c & 3) * 8;
            *(uint4*)(Bs + row * 40 + kc) =
                *(const uint4*)(B2T + (size_t)(n0 + row) * K3 + kt + kc);
        }
        __syncthreads();

#pragma unroll
        for (int ks = 0; ks < 2; ++ks) {
            const int K0 = ks * 16;
            unsigned int a[2][4], b[2][4];
#pragma unroll
            for (int mf = 0; mf < 2; ++mf) {
                int row = wm * 32 + mf * 16 + (lane & 15);
                int col = K0 + (lane >> 4) * 8;
                unsigned int ad = smem_u32(As + row * 40 + col);
                asm volatile("ldmatrix.sync.aligned.m8n8.x4.shared.b16 {%0,%1,%2,%3}, [%4];"
                             : "=r"(a[mf][0]), "=r"(a[mf][1]), "=r"(a[mf][2]), "=r"(a[mf][3])
                             : "r"(ad));
            }
#pragma unroll
            for (int g = 0; g < 2; ++g) {
                int grp = lane >> 3;
                int row = wn * 32 + g * 16 + (lane & 7) + ((grp >> 1) * 8);
                int col = K0 + (grp & 1) * 8;
                unsigned int ad = smem_u32(Bs + row * 40 + col);
                asm volatile("ldmatrix.sync.aligned.m8n8.x4.shared.b16 {%0,%1,%2,%3}, [%4];"
                             : "=r"(b[g][0]), "=r"(b[g][1]), "=r"(b[g][2]), "=r"(b[g][3])
                             : "r"(ad));
            }
#pragma unroll
            for (int mf = 0; mf < 2; ++mf)
#pragma unroll
                for (int nf = 0; nf < 4; ++nf) {
                    unsigned int b0 = b[nf >> 1][(nf & 1) * 2];
                    unsigned int b1 = b[nf >> 1][(nf & 1) * 2 + 1];
                    asm volatile(
                        "mma.sync.aligned.m16n8k16.row.col.f32.bf16.bf16.f32 "
                        "{%0,%1,%2,%3}, {%4,%5,%6,%7}, {%8,%9}, {%0,%1,%2,%3};"
                        : "+f"(acc[mf][nf][0]), "+f"(acc[mf][nf][1]),
                          "+f"(acc[mf][nf][2]), "+f"(acc[mf][nf][3])
                        : "r"(a[mf][0]), "r"(a[mf][1]), "r"(a[mf][2]), "r"(a[mf][3]),
                          "r"(b0), "r"(b1));
                }
        }
        __syncthreads();
    }

    // epilogue: add bias, write theta (skip padded col 4095)
#pragma unroll
    for (int mf = 0; mf < 2; ++mf) {
        int gm = m0 + wm * 32 + mf * 16 + (lane >> 2);
#pragma unroll
        for (int nf = 0; nf < 4; ++nf) {
            int gn = n0 + wn * 32 + nf * 8 + (lane & 3) * 2;
            if (gn < NGEN)     C[(size_t)gm * NGEN + gn]           = acc[mf][nf][0] + bias[gn];
            if (gn + 1 < NGEN) C[(size_t)gm * NGEN + gn + 1]       = acc[mf][nf][1] + bias[gn + 1];
            if (gn < NGEN)     C[(size_t)(gm + 8) * NGEN + gn]     = acc[mf][nf][2] + bias[gn];
            if (gn + 1 < NGEN) C[(size_t)(gm + 8) * NGEN + gn + 1] = acc[mf][nf][3] + bias[gn + 1];
        }
    }
}

// ---------------------------------------------------------------------------
// Slim head-hidden: h = silu(q @ Wv1 + bv1), q: 512x15, Wv1: 15x256
// ---------------------------------------------------------------------------
__global__ void __launch_bounds__(256) head_hidden_kernel(
    const float* __restrict__ q, const float* __restrict__ Wv1,
    const float* __restrict__ bv1, float* __restrict__ h)
{
    __shared__ float qs[NOBS];
    const int m = blockIdx.x, n = threadIdx.x;
    if (n < NOBS) qs[n] = q[m * NOBS + n];
    __syncthreads();
    float a = bv1[n];
#pragma unroll
    for (int k = 0; k < NOBS; ++k) a += qs[k] * Wv1[k * HID + n];
    h[m * HID + n] = silu_f(a);
}

// ---------------------------------------------------------------------------
// Physics kernel (unchanged from R8 passing version)
// ---------------------------------------------------------------------------
__device__ __forceinline__ int spread6(int x) {
    return (x & 1) | ((x & 2) << 1) | ((x & 4) << 2) |
           ((x & 8) << 3) | ((x & 16) << 4) | ((x & 32) << 5);
}

__global__ void __launch_bounds__(128, 4) physics_kernel(
    const float* __restrict__ theta_g,
    const float* __restrict__ Aoff, const float* __restrict__ Boff,
    const float* __restrict__ Ddiag, float* __restrict__ qout)
{
    extern __shared__ float sm[];
    float* th   = sm;
    float* Hre  = th + 4096;
    float* Him  = Hre + DIM * HPITCH;
    float* vre  = Him + DIM * HPITCH;
    float* vim  = vre + 3 * DIM;
    float* psr  = vim + 3 * DIM;
    float* psii = psr + DIM;
    float* cRe  = psii + DIM;
    float* cIm  = cRe + (KMAX + 1);
    float* red  = cIm + (KMAX + 1);

    __shared__ float sInvR, sRbase;
    __shared__ int sK, sOK;

    const int item = blockIdx.x;
    const int tid  = threadIdx.x;
    const int lane = tid & 31;
    const int warp = tid >> 5;

    const float* tg = theta_g + (size_t)item * NGEN;
    float acc = 0.0f;
    if (tid == 0) th[0] = 0.0f;
    for (int i = tid; i < NGEN; i += 128) {
        float v = tg[i];
        th[i + 1] = v;
        acc += v * v;
    }
#pragma unroll
    for (int o = 16; o >= 1; o >>= 1) acc += __shfl_xor_sync(0xffffffffu, acc, o);
    if (lane == 0) red[warp] = acc;
    __syncthreads();
    if (tid == 0) {
        float S = red[0] + red[1] + red[2] + red[3];
        sRbase = 2.3f * sqrtf(S) + 1.5f;
    }

#pragma unroll 1
    for (int t = 0; t < 16; ++t) {
        int a = (warp << 4) | t;
        float re[2], im[2];
#pragma unroll
        for (int h = 0; h < 2; ++h) {
            int b = lane + (h << 5);
            int m1 = (spread6(b) << 1) | spread6(a ^ b);
            float v = th[m1];
            int ph = __popc(a & b) & 3;
            re[h] = (ph == 0) ? v : ((ph == 2) ? -v : 0.0f);
            im[h] = (ph == 1) ? v : ((ph == 3) ? -v : 0.0f);
        }
#pragma unroll
        for (int st = 0; st < 5; ++st) {
            int msk = 1 << st;
            bool up = (lane & msk) != 0;
#pragma unroll
            for (int h = 0; h < 2; ++h) {
                float orr = __shfl_xor_sync(0xffffffffu, re[h], msk);
                float oii = __shfl_xor_sync(0xffffffffu, im[h], msk);
                re[h] = up ? (orr - re[h]) : (re[h] + orr);
                im[h] = up ? (oii - im[h]) : (im[h] + oii);
            }
        }
        float r0v = re[0] + re[1], r1v = re[0] - re[1];
        float i0v = im[0] + im[1], i1v = im[0] - im[1];
        int c0 = lane, c1 = lane | 32;
        Hre[(c0 ^ a) * HPITCH + c0] = r0v; Him[(c0 ^ a) * HPITCH + c0] = i0v;
        Hre[(c1 ^ a) * HPITCH + c1] = r1v; Him[(c1 ^ a) * HPITCH + c1] = i1v;
    }
    __syncthreads();

    const int qc = tid & 3, rp = tid >> 2;
    const int r0 = rp * 2, r1 = r0 + 1, cb = qc * 16;
    unsigned long long Ar0[8], Ai0[8], Ar1[8], Ai1[8];
#pragma unroll
    for (int p = 0; p < 8; ++p) {
        int c = cb + 2 * p;
        Ar0[p] = pk2(Hre[r0 * HPITCH + c], Hre[r0 * HPITCH + c + 1]);
        Ai0[p] = pk2(Him[r0 * HPITCH + c], Him[r0 * HPITCH + c + 1]);
        Ar1[p] = pk2(Hre[r1 * HPITCH + c], Hre[r1 * HPITCH + c + 1]);
        Ai1[p] = pk2(Him[r1 * HPITCH + c], Him[r1 * HPITCH + c + 1]);
    }

    for (int att = 0; att < 3; ++att) {
        if (tid == 0) {
            float R = sRbase;
            for (int i = 0; i < att; ++i) R *= 1.45f;
            int k = (int)ceilf(R) + 2; if (k < 10) k = 10;
            while (k < KMAX - 8 && (float)k * logf(0.73576f * (float)k / R) < 23.0f) k += 2;
            k += 6; if (k > KMAX) k = KMAX;
            sK = k; sInvR = 1.0f / R;
            const float twoInvR = 2.0f / R;
            const int M = k + 14;
            float jp = 0.0f, jc = 1e-20f;
            for (int kk = M - 1; kk >= 0; --kk) {
                float jm = (float)(kk + 1) * twoInvR * jc - jp;
                jp = jc; jc = jm;
                if (fabsf(jc) > 1e30f) {
                    jc *= 1e-30f; jp *= 1e-30f;
                    for (int i = kk + 1; i <= k; ++i) cRe[i] *= 1e-30f;
                }
                if (kk <= k) cRe[kk] = jc;
            }
            float sum = cRe[0];
            for (int i = 2; i <= k; i += 2) sum += 2.0f * cRe[i];
            float scl = 1.0f / sum;
            for (int kk = 0; kk <= k; ++kk) {
                float tw = ((kk == 0) ? 1.0f : 2.0f) * cRe[kk] * scl;
                int m4 = kk & 3;
                cRe[kk] = (m4 == 0) ? tw : ((m4 == 2) ? -tw : 0.0f);
                cIm[kk] = (m4 == 1) ? tw : ((m4 == 3) ? -tw : 0.0f);
            }
        }
        if (tid < DIM) {
            vre[tid] = 0.0f;        vim[tid] = 0.0f;
            vre[DIM + tid] = (tid == 0) ? 1.0f : 0.0f;
            vim[DIM + tid] = 0.0f;
            psr[tid] = 0.0f;        psii[tid] = 0.0f;
        }
        __syncthreads();

        const int K = sK;
        const float invR = sInvR;
        int ip = 0, ic = 1, in_ = 2;

        for (int k = 1; k <= K; ++k) {
            const float* xr = vre + ic * DIM;
            const float* xi = vim + ic * DIM;
            unsigned long long aR0 = 0, aM0 = 0, aIa0 = 0, aIb0 = 0;
            unsigned long long aR1 = 0, aM1 = 0, aIa1 = 0, aIb1 = 0;
#pragma unroll
            for (int p = 0; p < 8; ++p) {
                unsigned long long Vr = *(const unsigned long long*)(xr + cb + 2 * p);
                unsigned long long Vi = *(const unsigned long long*)(xi + cb + 2 * p);
                FMA2(aR0,  Ar0[p], Vr); FMA2(aM0,  Ai0[p], Vi);
                FMA2(aIa0, Ar0[p], Vi); FMA2(aIb0, Ai0[p], Vr);
                FMA2(aR1,  Ar1[p], Vr); FMA2(aM1,  Ai1[p], Vi);
                FMA2(aIa1, Ar1[p], Vi); FMA2(aIb1, Ai1[p], Vr);
            }
            float u, v, hr0, hi0, hr1, hi1;
            upk2(aR0, u, v);  hr0 = u + v;  upk2(aM0, u, v);  hr0 -= u + v;
            upk2(aIa0, u, v); hi0 = u + v;  upk2(aIb0, u, v); hi0 += u + v;
            upk2(aR1, u, v);  hr1 = u + v;  upk2(aM1, u, v);  hr1 -= u + v;
            upk2(aIa1, u, v); hi1 = u + v;  upk2(aIb1, u, v); hi1 += u + v;
#pragma unroll
            for (int m = 1; m <= 2; m <<= 1) {
                hr0 += __shfl_xor_sync(0xffffffffu, hr0, m);
                hi0 += __shfl_xor_sync(0xffffffffu, hi0, m);
                hr1 += __shfl_xor_sync(0xffffffffu, hr1, m);
                hi1 += __shfl_xor_sync(0xffffffffu, hi1, m);
            }
            if (qc == 0) {
                float s = ((k == 1) ? 1.0f : 2.0f) * invR;
                vre[in_ * DIM + r0] = s * hr0 - vre[ip * DIM + r0];
                vim[in_ * DIM + r0] = s * hi0 - vim[ip * DIM + r0];
                vre[in_ * DIM + r1] = s * hr1 - vre[ip * DIM + r1];
                vim[in_ * DIM + r1] = s * hi1 - vim[ip * DIM + r1];
            } else if (qc == 1) {
                float cr = cRe[k - 1], ci = cIm[k - 1];
                float a = xr[r0], b = xi[r0];
                psr[r0] += cr * a - ci * b;  psii[r0] += cr * b + ci * a;
                a = xr[r1]; b = xi[r1];
                psr[r1] += cr * a - ci * b;  psii[r1] += cr * b + ci * a;
            }
            __syncthreads();
            int t = ip; ip = ic; ic = in_; in_ = t;
        }
        if (qc == 1) {
            float cr = cRe[K], ci = cIm[K];
            const float* xr = vre + ic * DIM;
            const float* xi = vim + ic * DIM;
            float a = xr[r0], b = xi[r0];
            psr[r0] += cr * a - ci * b;  psii[r0] += cr * b + ci * a;
            a = xr[r1]; b = xi[r1];
            psr[r1] += cr * a - ci * b;  psii[r1] += cr * b + ci * a;
        }
        __syncthreads();

        if (tid < 32) {
            float a = psr[tid], b = psii[tid], c = psr[tid + 32], d = psii[tid + 32];
            float n = a * a + b * b + c * c + d * d;
#pragma unroll
            for (int o = 16; o >= 1; o >>= 1) n += __shfl_xor_sync(0xffffffffu, n, o);
            if (tid == 0) sOK = (fabsf(n - 1.0f) < 2e-4f) ? 1 : 0;
        }
        __syncthreads();
        if (sOK) break;
    }

    if (tid < NOBS) {
        const int w = tid;
        const int pA = 5 - c_wa[w], pB = 5 - c_wb[w];
        const int bitA = 1 << pA, bitB = 1 << pB;
        float d0 = 0, d1 = 0, d2 = 0, d3 = 0;
        float orr[6] = {0, 0, 0, 0, 0, 0};
        float oim[6] = {0, 0, 0, 0, 0, 0};
        for (int r = 0; r < 16; ++r) {
            int s = 0, rb = r;
#pragma unroll
            for (int p = 0; p < 6; ++p) {
                if (p != pA && p != pB) { s |= (rb & 1) << p; rb >>= 1; }
            }
            float2 p0 = make_float2(psr[s],               psii[s]);
            float2 p1 = make_float2(psr[s | bitB],        psii[s | bitB]);
            float2 p2 = make_float2(psr[s | bitA],        psii[s | bitA]);
            float2 p3 = make_float2(psr[s | bitA | bitB], psii[s | bitA | bitB]);
            d0 += p0.x * p0.x + p0.y * p0.y;
            d1 += p1.x * p1.x + p1.y * p1.y;
            d2 += p2.x * p2.x + p2.y * p2.y;
            d3 += p3.x * p3.x + p3.y * p3.y;
            orr[0] += p1.x * p0.x + p1.y * p0.y;  oim[0] += p1.y * p0.x - p1.x * p0.y;
            orr[1] += p2.x * p0.x + p2.y * p0.y;  oim[1] += p2.y * p0.x - p2.x * p0.y;
            orr[2] += p2.x * p1.x + p2.y * p1.y;  oim[2] += p2.y * p1.x - p2.x * p1.y;
            orr[3] += p3.x * p0.x + p3.y * p0.y;  oim[3] += p3.y * p0.x - p3.x * p0.y;
            orr[4] += p3.x * p1.x + p3.y * p1.y;  oim[4] += p3.y * p1.x - p3.x * p1.y;
            orr[5] += p3.x * p2.x + p3.y * p2.y;  oim[5] += p3.y * p2.x - p3.x * p2.y;
        }
        const float* Ao = Aoff + w * 6;
        const float* Bo = Boff + w * 6;
        const float* Dd = Ddiag + w * 4;
        float q = 2.0f * (Dd[1] * d0 + Dd[2] * d1 + Dd[3] * d2);
#pragma unroll
        for (int c = 0; c < 6; ++c)
            q += 2.0f * (Ao[c] * orr[c] + Bo[c] * oim[c]);
        qout[item * NOBS + w] = q;
    }
}

// ---------------------------------------------------------------------------
extern "C" void kernel_launch(void* const* d_in, const int* in_sizes, int n_in,
                              void* d_out, int out_size)
{
    const float* x     = (const float*)d_in[0];
    const float* W1    = (const float*)d_in[1];
    const float* b1    = (const float*)d_in[2];
    const float* W2    = (const float*)d_in[3];
    const float* b2    = (const float*)d_in[4];
    const float* Aoff  = (const float*)d_in[5];
    const float* Boff  = (const float*)d_in[6];
    const float* Ddiag = (const float*)d_in[7];
    const float* Wv1   = (const float*)d_in[8];
    const float* bv1   = (const float*)d_in[9];
    const float* Wv2   = (const float*)d_in[10];
    const float* bv2   = (const float*)d_in[11];
    float* out = (float*)d_out;

    float* hbuf;  cudaGetSymbolAddress((void**)&hbuf,  g_h);
    float* thbuf; cudaGetSymbolAddress((void**)&thbuf, g_theta);
    float* qbuf;  cudaGetSymbolAddress((void**)&qbuf,  g_q);
    __nv_bfloat16* a2buf;  cudaGetSymbolAddress((void**)&a2buf,  g_A2);
    __nv_bfloat16* b2tbuf; cudaGetSymbolAddress((void**)&b2tbuf, g_B2T);

    const int smemPhys = (4096 + 2 * DIM * HPITCH + 6 * DIM + 2 * DIM +
                          2 * (KMAX + 1) + 16) * (int)sizeof(float);
    static int attrSet = 0;
    if (!attrSet) {
        cudaFuncSetAttribute(physics_kernel,
                             cudaFuncAttributeMaxDynamicSharedMemorySize, smemPhys);
        attrSet = 1;
    }

    // 1) enc hidden: silu(x @ W1 + b1) : 512x768 @ 768x256
    {
        dim3 grid(HID / 16, BATCH / 64);
        gemm_kernel<64, 16, 32, 4, 2, true><<<grid, 128>>>(x, W1, b1, hbuf, BATCH, HID, KIN);
    }
    // 2a) split activations into bf16 hi/hi/lo
    splitA_kernel<<<BATCH, 256>>>(hbuf, a2buf);
    // 2b) transpose+split W2 into n-major bf16 [hi|lo|hi]
    {
        dim3 grid(NPAD / 32, HID / 32);
        transposeB_kernel<<<grid, dim3(32, 8)>>>(W2, b2tbuf);
    }
    // 2c) theta = A2 @ B2T^T + b2 on tensor cores (3-product bf16 split)
    {
        dim3 grid(NPAD / 128, BATCH / 64);
        mma_gemm2<<<grid, 256>>>(a2buf, b2tbuf, b2, thbuf);
    }
    // 3) physics: theta -> q
    physics_kernel<<<BATCH, 128, smemPhys>>>(thbuf, Aoff, Boff, Ddiag, qbuf);
    // 4) head hidden: silu(q @ Wv1 + bv1) — slim direct kernel
    head_hidden_kernel<<<BATCH, HID>>>(qbuf, Wv1, bv1, hbuf);
    // 5) out = hh @ Wv2 + bv2 : 512x256 @ 256x512
    {
        dim3 grid(COUT / 32, BATCH / 64);
        gemm_kernel<64, 32, 32, 4, 4, false><<<grid, 128>>>(hbuf, Wv2, bv2, out, BATCH, COUT, HID);
    }
}

// round 14
// speedup vs baseline: 1.9704x; 1.2511x over previous
#include <cuda_runtime.h>
#include <cuda_bf16.h>
#include <cstdint>
#include <math.h>

#define BATCH 512
#define NGEN  4095
#define HID   256
#define KIN   768
#define NOBS  15
#define COUT  512
#define DIM   64
#define KMAX  128
#define HPITCH 65

// ---------------- scratch (device globals; no allocations allowed) ----------
__device__ float g_theta[BATCH * NGEN];
__device__ float g_q[BATCH * NOBS];
__device__ __nv_bfloat16 g_A1[BATCH * 3 * KIN];    // x split       (512 x 2304)
__device__ __nv_bfloat16 g_B1T[HID * 3 * KIN];     // W1^T split    (256 x 2304)
__device__ __nv_bfloat16 g_A2[BATCH * 3 * HID];    // h split       (512 x 768)
__device__ __nv_bfloat16 g_B2T[4096 * 3 * HID];    // W2^T split    (4096 x 768)
__device__ __nv_bfloat16 g_A5[BATCH * 3 * HID];    // h5 split      (512 x 768)
__device__ __nv_bfloat16 g_B5T[COUT * 3 * HID];    // Wv2^T split   (512 x 768)

// wire pairs: combinations(range(6), 2) in order
__constant__ int c_wa[NOBS] = {0,0,0,0,0,1,1,1,1,2,2,2,3,3,4};
__constant__ int c_wb[NOBS] = {1,2,3,4,5,2,3,4,5,3,4,5,4,5,5};

__device__ __forceinline__ float silu_f(float x) { return x / (1.0f + expf(-x)); }

// packed f32x2 helpers
__device__ __forceinline__ unsigned long long pk2(float a, float b) {
    unsigned long long r;
    asm("mov.b64 %0,{%1,%2};" : "=l"(r) : "f"(a), "f"(b));
    return r;
}
__device__ __forceinline__ void upk2(unsigned long long v, float& a, float& b) {
    asm("mov.b64 {%0,%1},%2;" : "=f"(a), "=f"(b) : "l"(v));
}
#define FMA2(acc, a, b) asm("fma.rn.f32x2 %0, %1, %2, %0;" : "+l"(acc) : "l"(a), "l"(b))

__device__ __forceinline__ unsigned int smem_u32(const void* p) {
    return (unsigned int)__cvta_generic_to_shared(p);
}

// ---------------------------------------------------------------------------
// splitAx: x (512 x 768 fp32) -> g_A1 rows [hi | hi | lo] (512 x 2304 bf16)
// ---------------------------------------------------------------------------
__global__ void splitAx_kernel(const float* __restrict__ x, __nv_bfloat16* __restrict__ A1)
{
    int idx = blockIdx.x * 256 + threadIdx.x;
    if (idx >= BATCH * KIN) return;
    int m = idx / KIN, k = idx - m * KIN;
    float v = x[idx];
    __nv_bfloat16 hi = __float2bfloat16_rn(v);
    __nv_bfloat16 lo = __float2bfloat16_rn(v - __bfloat162float(hi));
    __nv_bfloat16* row = A1 + (size_t)m * (3 * KIN);
    row[k] = hi; row[KIN + k] = hi; row[2 * KIN + k] = lo;
}

// ---------------------------------------------------------------------------
// Generic transpose+split: W (K x N fp32, row-major) -> BT (Npad x 3K bf16)
// row n: [hi(k) | lo(k) | hi(k)]. grid (Npad/32, K/32), block (32, 8).
// ---------------------------------------------------------------------------
__global__ void transposeB_kernel(const float* __restrict__ W, __nv_bfloat16* __restrict__ BT,
                                  int K, int N)
{
    __shared__ float tile[32][33];
    const int n0 = blockIdx.x * 32;
    const int k0 = blockIdx.y * 32;
    const int tx = threadIdx.x, ty = threadIdx.y;
#pragma unroll
    for (int j = 0; j < 4; ++j) {
        int k = k0 + ty + j * 8;
        int n = n0 + tx;
        tile[ty + j * 8][tx] = (n < N) ? W[(size_t)k * N + n] : 0.0f;
    }
    __syncthreads();
#pragma unroll
    for (int j = 0; j < 4; ++j) {
        int n = n0 + ty + j * 8;
        int k = k0 + tx;
        float v = tile[tx][ty + j * 8];
        __nv_bfloat16 hi = __float2bfloat16_rn(v);
        __nv_bfloat16 lo = __float2bfloat16_rn(v - __bfloat162float(hi));
        __nv_bfloat16* row = BT + (size_t)n * (3 * K);
        row[k] = hi; row[K + k] = lo; row[2 * K + k] = hi;
    }
}

// ---------------------------------------------------------------------------
// Generic tensor-core GEMM on bf16 3-product split operands.
// C(M x Nreal) = A(M x K3) @ B(Npad x K3)^T + bias
// 256 threads (8 warps, (BM/WM) x (BN/WN) warp grid), BK=32, pitch-40 smem.
// OUT=0: fp32 write with ldc.  OUT=1: silu + [hi|hi|lo] bf16 split write
// (row stride 3*Nreal).
// ---------------------------------------------------------------------------
template<int BM, int BN, int WM, int WN, int OUT>
__global__ void __launch_bounds__(256) mma_gemm(
    const __nv_bfloat16* __restrict__ A, const __nv_bfloat16* __restrict__ B,
    const float* __restrict__ bias, void* __restrict__ Cout,
    int Nreal, int K3, int ldc)
{
    constexpr int WC = BN / WN;            // warp cols
    constexpr int MF = WM / 16;
    constexpr int NF = WN / 8;
    constexpr int NG = WN / 16;            // b x4-ldmatrix groups
    static_assert((BM / WM) * WC == 8, "8 warps");

    __shared__ __align__(16) __nv_bfloat16 As[BM * 40];
    __shared__ __align__(16) __nv_bfloat16 Bs[BN * 40];

    const int tid  = threadIdx.x;
    const int lane = tid & 31;
    const int w    = tid >> 5;
    const int wm   = w / WC;
    const int wn   = w % WC;
    const int m0   = blockIdx.y * BM;
    const int n0   = blockIdx.x * BN;

    float acc[MF][NF][4];
#pragma unroll
    for (int i = 0; i < MF; i++)
#pragma unroll
        for (int j = 0; j < NF; j++)
#pragma unroll
            for (int r = 0; r < 4; r++) acc[i][j][r] = 0.0f;

    for (int kt = 0; kt < K3; kt += 32) {
#pragma unroll
        for (int i = tid; i < BM * 4; i += 256) {
            int row = i >> 2, kc = (i & 3) * 8;
            *(uint4*)(As + row * 40 + kc) =
                *(const uint4*)(A + (size_t)(m0 + row) * K3 + kt + kc);
        }
#pragma unroll
        for (int i = tid; i < BN * 4; i += 256) {
            int row = i >> 2, kc = (i & 3) * 8;
            *(uint4*)(Bs + row * 40 + kc) =
                *(const uint4*)(B + (size_t)(n0 + row) * K3 + kt + kc);
        }
        __syncthreads();

#pragma unroll
        for (int ks = 0; ks < 2; ++ks) {
            const int K0 = ks * 16;
            unsigned int a[MF][4], b[NG][4];
#pragma unroll
            for (int mf = 0; mf < MF; ++mf) {
                int row = wm * WM + mf * 16 + (lane & 15);
                int col = K0 + (lane >> 4) * 8;
                unsigned int ad = smem_u32(As + row * 40 + col);
                asm volatile("ldmatrix.sync.aligned.m8n8.x4.shared.b16 {%0,%1,%2,%3}, [%4];"
                             : "=r"(a[mf][0]), "=r"(a[mf][1]), "=r"(a[mf][2]), "=r"(a[mf][3])
                             : "r"(ad));
            }
#pragma unroll
            for (int g = 0; g < NG; ++g) {
                int grp = lane >> 3;
                int row = wn * WN + g * 16 + (lane & 7) + ((grp >> 1) * 8);
                int col = K0 + (grp & 1) * 8;
                unsigned int ad = smem_u32(Bs + row * 40 + col);
                asm volatile("ldmatrix.sync.aligned.m8n8.x4.shared.b16 {%0,%1,%2,%3}, [%4];"
                             : "=r"(b[g][0]), "=r"(b[g][1]), "=r"(b[g][2]), "=r"(b[g][3])
                             : "r"(ad));
            }
#pragma unroll
            for (int mf = 0; mf < MF; ++mf)
#pragma unroll
                for (int nf = 0; nf < NF; ++nf) {
                    unsigned int b0 = b[nf >> 1][(nf & 1) * 2];
                    unsigned int b1 = b[nf >> 1][(nf & 1) * 2 + 1];
                    asm volatile(
                        "mma.sync.aligned.m16n8k16.row.col.f32.bf16.bf16.f32 "
                        "{%0,%1,%2,%3}, {%4,%5,%6,%7}, {%8,%9}, {%0,%1,%2,%3};"
                        : "+f"(acc[mf][nf][0]), "+f"(acc[mf][nf][1]),
                          "+f"(acc[mf][nf][2]), "+f"(acc[mf][nf][3])
                        : "r"(a[mf][0]), "r"(a[mf][1]), "r"(a[mf][2]), "r"(a[mf][3]),
                          "r"(b0), "r"(b1));
                }
        }
        __syncthreads();
    }

#pragma unroll
    for (int mf = 0; mf < MF; ++mf) {
#pragma unroll
        for (int half = 0; half < 2; ++half) {
            int gm = m0 + wm * WM + mf * 16 + (lane >> 2) + half * 8;
#pragma unroll
            for (int nf = 0; nf < NF; ++nf) {
                int gn = n0 + wn * WN + nf * 8 + (lane & 3) * 2;
#pragma unroll
                for (int e = 0; e < 2; ++e) {
                    int n = gn + e;
                    if (n >= Nreal) continue;
                    float v = acc[mf][nf][half * 2 + e] + bias[n];
                    if (OUT == 0) {
                        ((float*)Cout)[(size_t)gm * ldc + n] = v;
                    } else {
                        v = silu_f(v);
                        __nv_bfloat16 hi = __float2bfloat16_rn(v);
                        __nv_bfloat16 lo = __float2bfloat16_rn(v - __bfloat162float(hi));
                        __nv_bfloat16* row = (__nv_bfloat16*)Cout + (size_t)gm * (3 * Nreal);
                        row[n] = hi; row[Nreal + n] = hi; row[2 * Nreal + n] = lo;
                    }
                }
            }
        }
    }
}

// ---------------------------------------------------------------------------
// Slim head-hidden: h5 = silu(q @ Wv1 + bv1) -> split bf16 [hi|hi|lo] in g_A5
// ---------------------------------------------------------------------------
__global__ void __launch_bounds__(256) head_hidden_kernel(
    const float* __restrict__ q, const float* __restrict__ Wv1,
    const float* __restrict__ bv1, __nv_bfloat16* __restrict__ A5)
{
    __shared__ float qs[NOBS];
    const int m = blockIdx.x, n = threadIdx.x;
    if (n < NOBS) qs[n] = q[m * NOBS + n];
    __syncthreads();
    float a = bv1[n];
#pragma unroll
    for (int k = 0; k < NOBS; ++k) a += qs[k] * Wv1[k * HID + n];
    float v = silu_f(a);
    __nv_bfloat16 hi = __float2bfloat16_rn(v);
    __nv_bfloat16 lo = __float2bfloat16_rn(v - __bfloat162float(hi));
    __nv_bfloat16* row = A5 + (size_t)m * (3 * HID);
    row[n] = hi; row[HID + n] = hi; row[2 * HID + n] = lo;
}

// ---------------------------------------------------------------------------
// Physics kernel (unchanged from R10 passing version)
// ---------------------------------------------------------------------------
__device__ __forceinline__ int spread6(int x) {
    return (x & 1) | ((x & 2) << 1) | ((x & 4) << 2) |
           ((x & 8) << 3) | ((x & 16) << 4) | ((x & 32) << 5);
}

__global__ void __launch_bounds__(128, 4) physics_kernel(
    const float* __restrict__ theta_g,
    const float* __restrict__ Aoff, const float* __restrict__ Boff,
    const float* __restrict__ Ddiag, float* __restrict__ qout)
{
    extern __shared__ float sm[];
    float* th   = sm;
    float* Hre  = th + 4096;
    float* Him  = Hre + DIM * HPITCH;
    float* vre  = Him + DIM * HPITCH;
    float* vim  = vre + 3 * DIM;
    float* psr  = vim + 3 * DIM;
    float* psii = psr + DIM;
    float* cRe  = psii + DIM;
    float* cIm  = cRe + (KMAX + 1);
    float* red  = cIm + (KMAX + 1);

    __shared__ float sInvR, sRbase;
    __shared__ int sK, sOK;

    const int item = blockIdx.x;
    const int tid  = threadIdx.x;
    const int lane = tid & 31;
    const int warp = tid >> 5;

    const float* tg = theta_g + (size_t)item * NGEN;
    float acc = 0.0f;
    if (tid == 0) th[0] = 0.0f;
    for (int i = tid; i < NGEN; i += 128) {
        float v = tg[i];
        th[i + 1] = v;
        acc += v * v;
    }
#pragma unroll
    for (int o = 16; o >= 1; o >>= 1) acc += __shfl_xor_sync(0xffffffffu, acc, o);
    if (lane == 0) red[warp] = acc;
    __syncthreads();
    if (tid == 0) {
        float S = red[0] + red[1] + red[2] + red[3];
        sRbase = 2.3f * sqrtf(S) + 1.5f;
    }

#pragma unroll 1
    for (int t = 0; t < 16; ++t) {
        int a = (warp << 4) | t;
        float re[2], im[2];
#pragma unroll
        for (int h = 0; h < 2; ++h) {
            int b = lane + (h << 5);
            int m1 = (spread6(b) << 1) | spread6(a ^ b);
            float v = th[m1];
            int ph = __popc(a & b) & 3;
            re[h] = (ph == 0) ? v : ((ph == 2) ? -v : 0.0f);
            im[h] = (ph == 1) ? v : ((ph == 3) ? -v : 0.0f);
        }
#pragma unroll
        for (int st = 0; st < 5; ++st) {
            int msk = 1 << st;
            bool up = (lane & msk) != 0;
#pragma unroll
            for (int h = 0; h < 2; ++h) {
                float orr = __shfl_xor_sync(0xffffffffu, re[h], msk);
                float oii = __shfl_xor_sync(0xffffffffu, im[h], msk);
                re[h] = up ? (orr - re[h]) : (re[h] + orr);
                im[h] = up ? (oii - im[h]) : (im[h] + oii);
            }
        }
        float r0v = re[0] + re[1], r1v = re[0] - re[1];
        float i0v = im[0] + im[1], i1v = im[0] - im[1];
        int c0 = lane, c1 = lane | 32;
        Hre[(c0 ^ a) * HPITCH + c0] = r0v; Him[(c0 ^ a) * HPITCH + c0] = i0v;
        Hre[(c1 ^ a) * HPITCH + c1] = r1v; Him[(c1 ^ a) * HPITCH + c1] = i1v;
    }
    __syncthreads();

    const int qc = tid & 3, rp = tid >> 2;
    const int r0 = rp * 2, r1 = r0 + 1, cb = qc * 16;
    unsigned long long Ar0[8], Ai0[8], Ar1[8], Ai1[8];
#pragma unroll
    for (int p = 0; p < 8; ++p) {
        int c = cb + 2 * p;
        Ar0[p] = pk2(Hre[r0 * HPITCH + c], Hre[r0 * HPITCH + c + 1]);
        Ai0[p] = pk2(Him[r0 * HPITCH + c], Him[r0 * HPITCH + c + 1]);
        Ar1[p] = pk2(Hre[r1 * HPITCH + c], Hre[r1 * HPITCH + c + 1]);
        Ai1[p] = pk2(Him[r1 * HPITCH + c], Him[r1 * HPITCH + c + 1]);
    }

    for (int att = 0; att < 3; ++att) {
        if (tid == 0) {
            float R = sRbase;
            for (int i = 0; i < att; ++i) R *= 1.45f;
            int k = (int)ceilf(R) + 2; if (k < 10) k = 10;
            while (k < KMAX - 8 && (float)k * logf(0.73576f * (float)k / R) < 23.0f) k += 2;
            k += 6; if (k > KMAX) k = KMAX;
            sK = k; sInvR = 1.0f / R;
            const float twoInvR = 2.0f / R;
            const int M = k + 14;
            float jp = 0.0f, jc = 1e-20f;
            for (int kk = M - 1; kk >= 0; --kk) {
                float jm = (float)(kk + 1) * twoInvR * jc - jp;
                jp = jc; jc = jm;
                if (fabsf(jc) > 1e30f) {
                    jc *= 1e-30f; jp *= 1e-30f;
                    for (int i = kk + 1; i <= k; ++i) cRe[i] *= 1e-30f;
                }
                if (kk <= k) cRe[kk] = jc;
            }
            float sum = cRe[0];
            for (int i = 2; i <= k; i += 2) sum += 2.0f * cRe[i];
            float scl = 1.0f / sum;
            for (int kk = 0; kk <= k; ++kk) {
                float tw = ((kk == 0) ? 1.0f : 2.0f) * cRe[kk] * scl;
                int m4 = kk & 3;
                cRe[kk] = (m4 == 0) ? tw : ((m4 == 2) ? -tw : 0.0f);
                cIm[kk] = (m4 == 1) ? tw : ((m4 == 3) ? -tw : 0.0f);
            }
        }
        if (tid < DIM) {
            vre[tid] = 0.0f;        vim[tid] = 0.0f;
            vre[DIM + tid] = (tid == 0) ? 1.0f : 0.0f;
            vim[DIM + tid] = 0.0f;
            psr[tid] = 0.0f;        psii[tid] = 0.0f;
        }
        __syncthreads();

        const int K = sK;
        const float invR = sInvR;
        int ip = 0, ic = 1, in_ = 2;

        for (int k = 1; k <= K; ++k) {
            const float* xr = vre + ic * DIM;
            const float* xi = vim + ic * DIM;
            unsigned long long aR0 = 0, aM0 = 0, aIa0 = 0, aIb0 = 0;
            unsigned long long aR1 = 0, aM1 = 0, aIa1 = 0, aIb1 = 0;
#pragma unroll
            for (int p = 0; p < 8; ++p) {
                unsigned long long Vr = *(const unsigned long long*)(xr + cb + 2 * p);
                unsigned long long Vi = *(const unsigned long long*)(xi + cb + 2 * p);
                FMA2(aR0,  Ar0[p], Vr); FMA2(aM0,  Ai0[p], Vi);
                FMA2(aIa0, Ar0[p], Vi); FMA2(aIb0, Ai0[p], Vr);
                FMA2(aR1,  Ar1[p], Vr); FMA2(aM1,  Ai1[p], Vi);
                FMA2(aIa1, Ar1[p], Vi); FMA2(aIb1, Ai1[p], Vr);
            }
            float u, v, hr0, hi0, hr1, hi1;
            upk2(aR0, u, v);  hr0 = u + v;  upk2(aM0, u, v);  hr0 -= u + v;
            upk2(aIa0, u, v); hi0 = u + v;  upk2(aIb0, u, v); hi0 += u + v;
            upk2(aR1, u, v);  hr1 = u + v;  upk2(aM1, u, v);  hr1 -= u + v;
            upk2(aIa1, u, v); hi1 = u + v;  upk2(aIb1, u, v); hi1 += u + v;
#pragma unroll
            for (int m = 1; m <= 2; m <<= 1) {
                hr0 += __shfl_xor_sync(0xffffffffu, hr0, m);
                hi0 += __shfl_xor_sync(0xffffffffu, hi0, m);
                hr1 += __shfl_xor_sync(0xffffffffu, hr1, m);
                hi1 += __shfl_xor_sync(0xffffffffu, hi1, m);
            }
            if (qc == 0) {
                float s = ((k == 1) ? 1.0f : 2.0f) * invR;
                vre[in_ * DIM + r0] = s * hr0 - vre[ip * DIM + r0];
                vim[in_ * DIM + r0] = s * hi0 - vim[ip * DIM + r0];
                vre[in_ * DIM + r1] = s * hr1 - vre[ip * DIM + r1];
                vim[in_ * DIM + r1] = s * hi1 - vim[ip * DIM + r1];
            } else if (qc == 1) {
                float cr = cRe[k - 1], ci = cIm[k - 1];
                float a = xr[r0], b = xi[r0];
                psr[r0] += cr * a - ci * b;  psii[r0] += cr * b + ci * a;
                a = xr[r1]; b = xi[r1];
                psr[r1] += cr * a - ci * b;  psii[r1] += cr * b + ci * a;
            }
            __syncthreads();
            int t = ip; ip = ic; ic = in_; in_ = t;
        }
        if (qc == 1) {
            float cr = cRe[K], ci = cIm[K];
            const float* xr = vre + ic * DIM;
            const float* xi = vim + ic * DIM;
            float a = xr[r0], b = xi[r0];
            psr[r0] += cr * a - ci * b;  psii[r0] += cr * b + ci * a;
            a = xr[r1]; b = xi[r1];
            psr[r1] += cr * a - ci * b;  psii[r1] += cr * b + ci * a;
        }
        __syncthreads();

        if (tid < 32) {
            float a = psr[tid], b = psii[tid], c = psr[tid + 32], d = psii[tid + 32];
            float n = a * a + b * b + c * c + d * d;
#pragma unroll
            for (int o = 16; o >= 1; o >>= 1) n += __shfl_xor_sync(0xffffffffu, n, o);
            if (tid == 0) sOK = (fabsf(n - 1.0f) < 2e-4f) ? 1 : 0;
        }
        __syncthreads();
        if (sOK) break;
    }

    if (tid < NOBS) {
        const int w = tid;
        const int pA = 5 - c_wa[w], pB = 5 - c_wb[w];
        const int bitA = 1 << pA, bitB = 1 << pB;
        float d0 = 0, d1 = 0, d2 = 0, d3 = 0;
        float orr[6] = {0, 0, 0, 0, 0, 0};
        float oim[6] = {0, 0, 0, 0, 0, 0};
        for (int r = 0; r < 16; ++r) {
            int s = 0, rb = r;
#pragma unroll
            for (int p = 0; p < 6; ++p) {
                if (p != pA && p != pB) { s |= (rb & 1) << p; rb >>= 1; }
            }
            float2 p0 = make_float2(psr[s],               psii[s]);
            float2 p1 = make_float2(psr[s | bitB],        psii[s | bitB]);
            float2 p2 = make_float2(psr[s | bitA],        psii[s | bitA]);
            float2 p3 = make_float2(psr[s | bitA | bitB], psii[s | bitA | bitB]);
            d0 += p0.x * p0.x + p0.y * p0.y;
            d1 += p1.x * p1.x + p1.y * p1.y;
            d2 += p2.x * p2.x + p2.y * p2.y;
            d3 += p3.x * p3.x + p3.y * p3.y;
            orr[0] += p1.x * p0.x + p1.y * p0.y;  oim[0] += p1.y * p0.x - p1.x * p0.y;
            orr[1] += p2.x * p0.x + p2.y * p0.y;  oim[1] += p2.y * p0.x - p2.x * p0.y;
            orr[2] += p2.x * p1.x + p2.y * p1.y;  oim[2] += p2.y * p1.x - p2.x * p1.y;
            orr[3] += p3.x * p0.x + p3.y * p0.y;  oim[3] += p3.y * p0.x - p3.x * p0.y;
            orr[4] += p3.x * p1.x + p3.y * p1.y;  oim[4] += p3.y * p1.x - p3.x * p1.y;
            orr[5] += p3.x * p2.x + p3.y * p2.y;  oim[5] += p3.y * p2.x - p3.x * p2.y;
        }
        const float* Ao = Aoff + w * 6;
        const float* Bo = Boff + w * 6;
        const float* Dd = Ddiag + w * 4;
        float q = 2.0f * (Dd[1] * d0 + Dd[2] * d1 + Dd[3] * d2);
#pragma unroll
        for (int c = 0; c < 6; ++c)
            q += 2.0f * (Ao[c] * orr[c] + Bo[c] * oim[c]);
        qout[item * NOBS + w] = q;
    }
}

// ---------------------------------------------------------------------------
extern "C" void kernel_launch(void* const* d_in, const int* in_sizes, int n_in,
                              void* d_out, int out_size)
{
    const float* x     = (const float*)d_in[0];
    const float* W1    = (const float*)d_in[1];
    const float* b1    = (const float*)d_in[2];
    const float* W2    = (const float*)d_in[3];
    const float* b2    = (const float*)d_in[4];
    const float* Aoff  = (const float*)d_in[5];
    const float* Boff  = (const float*)d_in[6];
    const float* Ddiag = (const float*)d_in[7];
    const float* Wv1   = (const float*)d_in[8];
    const float* bv1   = (const float*)d_in[9];
    const float* Wv2   = (const float*)d_in[10];
    const float* bv2   = (const float*)d_in[11];
    float* out = (float*)d_out;

    float* thbuf; cudaGetSymbolAddress((void**)&thbuf, g_theta);
    float* qbuf;  cudaGetSymbolAddress((void**)&qbuf,  g_q);
    __nv_bfloat16 *a1, *b1t, *a2, *b2t, *a5, *b5t;
    cudaGetSymbolAddress((void**)&a1,  g_A1);
    cudaGetSymbolAddress((void**)&b1t, g_B1T);
    cudaGetSymbolAddress((void**)&a2,  g_A2);
    cudaGetSymbolAddress((void**)&b2t, g_B2T);
    cudaGetSymbolAddress((void**)&a5,  g_A5);
    cudaGetSymbolAddress((void**)&b5t, g_B5T);

    const int smemPhys = (4096 + 2 * DIM * HPITCH + 6 * DIM + 2 * DIM +
                          2 * (KMAX + 1) + 16) * (int)sizeof(float);
    static int attrSet = 0;
    if (!attrSet) {
        cudaFuncSetAttribute(physics_kernel,
                             cudaFuncAttributeMaxDynamicSharedMemorySize, smemPhys);
        attrSet = 1;
    }

    // prep: split x; transpose+split W1, W2, Wv2
    splitAx_kernel<<<(BATCH * KIN + 255) / 256, 256>>>(x, a1);
    transposeB_kernel<<<dim3(HID / 32, KIN / 32),  dim3(32, 8)>>>(W1,  b1t, KIN, HID);
    transposeB_kernel<<<dim3(4096 / 32, HID / 32), dim3(32, 8)>>>(W2,  b2t, HID, NGEN);
    transposeB_kernel<<<dim3(COUT / 32, HID / 32), dim3(32, 8)>>>(Wv2, b5t, HID, COUT);

    // 1) h-split = silu(x @ W1 + b1) -> g_A2 (split)  [M=512, N=256, K3=2304]
    mma_gemm<32, 128, 32, 16, 1><<<dim3(HID / 128, BATCH / 32), 256>>>(
        a1, b1t, b1, a2, HID, 3 * KIN, 0);
    // 2) theta = h @ W2 + b2  [M=512, N=4095 (pad 4096), K3=768]
    mma_gemm<64, 128, 32, 32, 0><<<dim3(4096 / 128, BATCH / 64), 256>>>(
        a2, b2t, b2, thbuf, NGEN, 3 * HID, NGEN);
    // 3) physics: theta -> q
    physics_kernel<<<BATCH, 128, smemPhys>>>(thbuf, Aoff, Boff, Ddiag, qbuf);
    // 4) h5-split = silu(q @ Wv1 + bv1) -> g_A5 (split)
    head_hidden_kernel<<<BATCH, HID>>>(qbuf, Wv1, bv1, a5);
    // 5) out = h5 @ Wv2 + bv2  [M=512, N=512, K3=768]
    mma_gemm<64, 128, 32, 32, 0><<<dim3(COUT / 128, BATCH / 64), 256>>>(
        a5, b5t, bv2, out, COUT, 3 * HID, COUT);
}